// round 10
// baseline (speedup 1.0000x reference)
#include <cuda_runtime.h>

#define DEV __device__ __forceinline__

// ---------------- shared-memory weight layout (floats) ----------------
static constexpr int OFF_WSELF = 0;                       // 15*128
static constexpr int OFF_BSELF = OFF_WSELF + 15 * 128;    // 128
static constexpr int OFF_WDYN  = OFF_BSELF + 128;         // 128*64
static constexpr int OFF_BDYN  = OFF_WDYN + 128 * 64;     // 64
static constexpr int OFF_HWH   = OFF_BDYN + 64;           // 3*3*16
static constexpr int OFF_HA1   = OFF_HWH + 144;           // 48
static constexpr int OFF_HA2   = OFF_HA1 + 48;            // 48
static constexpr int OFF_HWO   = OFF_HA2 + 48;            // 48*64
static constexpr int OFF_HWA1  = OFF_HWO + 48 * 64;       // 48  (hWo @ hao1)
static constexpr int OFF_HWA2  = OFF_HWA1 + 48;           // 48  (hWo @ hao2)
static constexpr int OFF_CWH   = OFF_HWA2 + 48;
static constexpr int OFF_CA1   = OFF_CWH + 144;
static constexpr int OFF_CA2   = OFF_CA1 + 48;
static constexpr int OFF_CWO   = OFF_CA2 + 48;
static constexpr int OFF_CWA1  = OFF_CWO + 48 * 64;
static constexpr int OFF_CWA2  = OFF_CWA1 + 48;
static constexpr int OFF_LW1   = OFF_CWA2 + 48;           // 108*64
static constexpr int OFF_LB1   = OFF_LW1 + 108 * 64;      // 64
static constexpr int OFF_LW2   = OFF_LB1 + 64;            // 64*64
static constexpr int OFF_LB2   = OFF_LW2 + 64 * 64;       // 64
static constexpr int OFF_CMW1  = OFF_LB2 + 64;            // 269*64
static constexpr int OFF_CMB1  = OFF_CMW1 + 269 * 64;     // 64
static constexpr int OFF_CMW2  = OFF_CMB1 + 64;           // 64*64
static constexpr int OFF_CMB2  = OFF_CMW2 + 64 * 64;      // 64
static constexpr int SMEM_FLOATS = OFF_CMB2 + 64;         // 49696 floats = 198784 B

static constexpr int OBS_STRIDE = 2064;   // 6 * 344
static constexpr int CUR = 5 * 344;       // 1720

static constexpr int ROWS_PER_BLOCK = 224;
static constexpr int BLOCK = 448;         // 2 threads per row
static constexpr int GRID  = 148;

DEV float lrelu2(float z)  { return z > 0.f ? z : 0.01f * z; }  // leaky(leaky(.,0.1),0.1)
DEV float lrelu02(float z) { return z > 0.f ? z : 0.2f  * z; }
DEV float eluf(float z)    { return z > 0.f ? z : (__expf(z) - 1.f); }

DEV void cp4(float* dst, const float* __restrict__ src, int n4, int tid, int bd) {
    float4* d = reinterpret_cast<float4*>(dst);
    const float4* sp = reinterpret_cast<const float4*>(src);
    for (int i = tid; i < n4; i += bd) d[i] = sp[i];
}

// Pair-split GEMV update: thread t (0/1) owns interleaved float4 chunks 2i+t of the
// 64-wide output row. acc[32] += v * row[owned 32 cols]. Even/odd lanes hit disjoint
// bank groups -> one wavefront serves the pair.
DEV void gv32(float (&acc)[32], float v, const float* row, int t) {
    const float4* w = reinterpret_cast<const float4*>(row);
    #pragma unroll
    for (int i = 0; i < 8; i++) {
        float4 q = w[2 * i + t];
        acc[4*i+0] = fmaf(v, q.x, acc[4*i+0]);
        acc[4*i+1] = fmaf(v, q.y, acc[4*i+1]);
        acc[4*i+2] = fmaf(v, q.z, acc[4*i+2]);
        acc[4*i+3] = fmaf(v, q.w, acc[4*i+3]);
    }
}

// acc[32] += stage[0..K-1] (full 64-wide multipliers in local mem) @ sW rows (owned cols).
DEV void gemv_stage32(float (&acc)[32], volatile const float* st, const float* sW, int K, int t) {
    #pragma unroll 1
    for (int k = 0; k < K; k++) {
        float v = st[k];
        gv32(acc, v, sW + k * 64, t);
    }
}

DEV void initAcc32(float (&acc)[32], const float* bias, int t) {
    const float4* bp = reinterpret_cast<const float4*>(bias);
    #pragma unroll
    for (int i = 0; i < 8; i++) {
        float4 q = bp[2 * i + t];
        acc[4*i+0] = q.x; acc[4*i+1] = q.y; acc[4*i+2] = q.z; acc[4*i+3] = q.w;
    }
}

// Build full 64-wide stage[] from own 32 values + partner's 32 (shfl.xor lane 1).
// Own value j lives at column 8i+4t+c (i=j/4, c=j%4); partner's at 8i+4(1-t)+c.
DEV void exchange_stage(volatile float* stage, const float (&own)[32], int t) {
    #pragma unroll
    for (int i = 0; i < 8; i++) {
        #pragma unroll
        for (int c = 0; c < 4; c++) {
            float v = own[4 * i + c];
            float p = __shfl_xor_sync(0xFFFFFFFFu, v, 1);
            stage[8 * i + 4 * t + c] = v;
            stage[8 * i + 4 * (1 - t) + c] = p;
        }
    }
}

// Star-GAT collapsed. Streams x2e/x2o into LOCAL arrays, accumulating layer-2
// attention dots on the fly. Returns blend weights we/wo. (Computed redundantly
// by both threads of a pair.)
template<int N>
DEV void gat_collapse(const float* __restrict__ xin,     // nodes 1..N-1, stride 6, first 3 floats
                      float e0, float e1, float e2,      // ego node coords
                      const float* s, int WH, int A1, int A2, int WA1, int WA2,
                      volatile float* lx2e, volatile float* lx2o,
                      float& we_out, float& wo_out)
{
    float d1e = 0.f, d2e = 0.f, d2o = 0.f;
    #pragma unroll 1
    for (int h = 0; h < 3; h++) {
        const float* Wh = s + WH + h * 48;   // [3][16]
        const float* a1 = s + A1 + h * 16;
        const float* a2 = s + A2 + h * 16;
        float h0[16];
        float s1 = 0.f, s20 = 0.f;
        #pragma unroll
        for (int t = 0; t < 16; t++) {
            float hv = fmaf(e0, Wh[t], fmaf(e1, Wh[16 + t], e2 * Wh[32 + t]));
            h0[t] = hv;
            s1  = fmaf(a1[t], hv, s1);
            s20 = fmaf(a2[t], hv, s20);
        }
        float w0 = __expf(lrelu02(s1 + s20));
        float den = w0;
        float ws[16];
        #pragma unroll
        for (int t = 0; t < 16; t++) ws[t] = w0 * h0[t];
        #pragma unroll 1
        for (int m = 0; m < N - 1; m++) {
            const float* xp = xin + m * 6;
            float x0 = xp[0], x1 = xp[1], x2v = xp[2];
            float hm[16]; float s2 = 0.f;
            #pragma unroll
            for (int t = 0; t < 16; t++) {
                float hv = fmaf(x0, Wh[t], fmaf(x1, Wh[16 + t], x2v * Wh[32 + t]));
                hm[t] = hv;
                s2 = fmaf(a2[t], hv, s2);
            }
            float wm = __expf(lrelu02(s1 + s2));
            den += wm;
            #pragma unroll
            for (int t = 0; t < 16; t++) ws[t] = fmaf(wm, hm[t], ws[t]);
        }
        float inv = __fdividef(1.f, den);
        #pragma unroll
        for (int t = 0; t < 16; t++) {
            float xe = eluf(ws[t] * inv);     // ego layer-1 output (concat heads)
            float xo = eluf(h0[t]);           // identical layer-1 output of every non-ego node
            d1e = fmaf(xe, s[WA1 + h * 16 + t], d1e);
            d2e = fmaf(xe, s[WA2 + h * 16 + t], d2e);
            d2o = fmaf(xo, s[WA2 + h * 16 + t], d2o);
            lx2e[h * 16 + t] = xe;
            lx2o[h * 16 + t] = xo;
        }
    }
    float we = __expf(lrelu02(d1e + d2e));
    float wo = (float)(N - 1) * __expf(lrelu02(d1e + d2o));
    float inv = __fdividef(1.f, we + wo);
    we_out = we * inv;
    wo_out = wo * inv;
}

__global__ void __launch_bounds__(BLOCK, 1) pred_kernel(
    const float* __restrict__ obs,
    const float* __restrict__ W_self, const float* __restrict__ b_self,
    const float* __restrict__ W_dyn,  const float* __restrict__ b_dyn,
    const float* __restrict__ hWh, const float* __restrict__ ha1, const float* __restrict__ ha2,
    const float* __restrict__ hWo, const float* __restrict__ hao1, const float* __restrict__ hao2,
    const float* __restrict__ cWh, const float* __restrict__ ca1v, const float* __restrict__ ca2v,
    const float* __restrict__ cWo, const float* __restrict__ cao1, const float* __restrict__ cao2,
    const float* __restrict__ lW1, const float* __restrict__ lb1,
    const float* __restrict__ lW2, const float* __restrict__ lb2,
    const float* __restrict__ cmW1, const float* __restrict__ cmb1,
    const float* __restrict__ cmW2, const float* __restrict__ cmb2,
    float* __restrict__ out, int B)
{
    extern __shared__ float s[];
    const int tid = threadIdx.x, bd = blockDim.x;

    cp4(s + OFF_WSELF, W_self, 15 * 128 / 4, tid, bd);
    cp4(s + OFF_BSELF, b_self, 128 / 4, tid, bd);
    cp4(s + OFF_WDYN,  W_dyn,  128 * 64 / 4, tid, bd);
    cp4(s + OFF_BDYN,  b_dyn,  64 / 4, tid, bd);
    cp4(s + OFF_HWH,   hWh,    144 / 4, tid, bd);
    cp4(s + OFF_HA1,   ha1,    48 / 4, tid, bd);
    cp4(s + OFF_HA2,   ha2,    48 / 4, tid, bd);
    cp4(s + OFF_HWO,   hWo,    48 * 64 / 4, tid, bd);
    cp4(s + OFF_CWH,   cWh,    144 / 4, tid, bd);
    cp4(s + OFF_CA1,   ca1v,   48 / 4, tid, bd);
    cp4(s + OFF_CA2,   ca2v,   48 / 4, tid, bd);
    cp4(s + OFF_CWO,   cWo,    48 * 64 / 4, tid, bd);
    cp4(s + OFF_LW1,   lW1,    108 * 64 / 4, tid, bd);
    cp4(s + OFF_LB1,   lb1,    64 / 4, tid, bd);
    cp4(s + OFF_LW2,   lW2,    64 * 64 / 4, tid, bd);
    cp4(s + OFF_LB2,   lb2,    64 / 4, tid, bd);
    cp4(s + OFF_CMW1,  cmW1,   269 * 64 / 4, tid, bd);
    cp4(s + OFF_CMB1,  cmb1,   64 / 4, tid, bd);
    cp4(s + OFF_CMW2,  cmW2,   64 * 64 / 4, tid, bd);
    cp4(s + OFF_CMB2,  cmb2,   64 / 4, tid, bd);

    // Precompute Wo@ao1 / Wo@ao2 for both GATs (48 values each)
    if (tid < 192) {
        int g = tid / 48;
        int r = tid - g * 48;
        const float* Wo = (g < 2) ? hWo : cWo;
        const float* ao = (g == 0) ? hao1 : (g == 1) ? hao2 : (g == 2) ? cao1 : cao2;
        int dst = (g == 0) ? OFF_HWA1 : (g == 1) ? OFF_HWA2 : (g == 2) ? OFF_CWA1 : OFF_CWA2;
        float sum = 0.f;
        #pragma unroll 1
        for (int j = 0; j < 64; j++) sum = fmaf(Wo[r * 64 + j], ao[j], sum);
        s[dst + r] = sum;
    }
    __syncthreads();

    const int t = tid & 1;                       // pair half (owns interleaved chunks 2i+t)
    int b = blockIdx.x * ROWS_PER_BLOCK + (tid >> 1);
    if (b >= B) b = B - 1;                       // clamp: keep all lanes alive for shfl
    const float* o = obs + (long long)b * OBS_STRIDE;

    volatile float stage[64];   // per-thread local staging for full-width GEMV multipliers
    volatile float lx2e[48];    // GAT ego-path features
    volatile float lx2o[48];    // GAT other-path features
    float ca[32];               // comb-MLP hidden accumulator (owned half, persists)
    float acc[32];              // working accumulator (owned half, reused)

    initAcc32(ca, s + OFF_CMB1, t);

    const float e0g = o[CUR + 234], e1g = o[CUR + 235], e2g = o[CUR + 236];

    // ----- HDV GAT (comb rows 64..127) -----
    {
        float we, wo;
        gat_collapse<13>(o + CUR + 0, e0g, e1g, e2g, s, OFF_HWH, OFF_HA1, OFF_HA2,
                         OFF_HWA1, OFF_HWA2, lx2e, lx2o, we, wo);
        #pragma unroll
        for (int j = 0; j < 32; j++) acc[j] = 0.f;
        #pragma unroll 1
        for (int k = 0; k < 48; k++) {
            float v = fmaf(we, lx2e[k], wo * lx2o[k]);
            gv32(acc, v, s + OFF_HWO + k * 64, t);
        }
        #pragma unroll
        for (int j = 0; j < 32; j++) acc[j] = eluf(acc[j]);
        exchange_stage(stage, acc, t);
    }
    gemv_stage32(ca, stage, s + OFF_CMW1 + 64 * 64, 64, t);

    // ----- CAV GAT (comb rows 128..191) -----
    {
        float we, wo;
        gat_collapse<9>(o + CUR + 72, e0g, e1g, e2g, s, OFF_CWH, OFF_CA1, OFF_CA2,
                        OFF_CWA1, OFF_CWA2, lx2e, lx2o, we, wo);
        #pragma unroll
        for (int j = 0; j < 32; j++) acc[j] = 0.f;
        #pragma unroll 1
        for (int k = 0; k < 48; k++) {
            float v = fmaf(we, lx2e[k], wo * lx2o[k]);
            gv32(acc, v, s + OFF_CWO + k * 64, t);
        }
        #pragma unroll
        for (int j = 0; j < 32; j++) acc[j] = eluf(acc[j]);
        exchange_stage(stage, acc, t);
    }
    gemv_stage32(ca, stage, s + OFF_CMW1 + 128 * 64, 64, t);

    // ----- ego feature (comb rows 0..63): leaky2(ehist@W_self+b_self)@W_dyn+b_dyn -----
    initAcc32(acc, s + OFF_BDYN, t);
    {
        float eh[15];
        #pragma unroll
        for (int st = 0; st < 5; st++) {
            const float* p = o + (st + 1) * 344 + 234;
            eh[st * 3 + 0] = p[0];
            eh[st * 3 + 1] = p[1];
            eh[st * 3 + 2] = p[2];
        }
        #pragma unroll 1
        for (int kg = 0; kg < 32; kg++) {   // 4 hidden columns at a time (float4 rows)
            float4 zb = reinterpret_cast<const float4*>(s + OFF_BSELF)[kg];
            float z0 = zb.x, z1 = zb.y, z2 = zb.z, z3 = zb.w;
            #pragma unroll
            for (int i = 0; i < 15; i++) {
                float4 w = reinterpret_cast<const float4*>(s + OFF_WSELF + i * 128)[kg];
                z0 = fmaf(eh[i], w.x, z0);
                z1 = fmaf(eh[i], w.y, z1);
                z2 = fmaf(eh[i], w.z, z2);
                z3 = fmaf(eh[i], w.w, z3);
            }
            gv32(acc, lrelu2(z0), s + OFF_WDYN + (4 * kg + 0) * 64, t);
            gv32(acc, lrelu2(z1), s + OFF_WDYN + (4 * kg + 1) * 64, t);
            gv32(acc, lrelu2(z2), s + OFF_WDYN + (4 * kg + 2) * 64, t);
            gv32(acc, lrelu2(z3), s + OFF_WDYN + (4 * kg + 3) * 64, t);
        }
    }
    exchange_stage(stage, acc, t);
    gemv_stage32(ca, stage, s + OFF_CMW1 + 0 * 64, 64, t);

    // ----- lane MLP (comb rows 192..255) -----
    initAcc32(acc, s + OFF_LB1, t);
    {
        const float4* lp = reinterpret_cast<const float4*>(o + CUR + 120);
        #pragma unroll 1
        for (int k4 = 0; k4 < 27; k4++) {
            float4 v = lp[k4];
            gv32(acc, v.x, s + OFF_LW1 + (4 * k4 + 0) * 64, t);
            gv32(acc, v.y, s + OFF_LW1 + (4 * k4 + 1) * 64, t);
            gv32(acc, v.z, s + OFF_LW1 + (4 * k4 + 2) * 64, t);
            gv32(acc, v.w, s + OFF_LW1 + (4 * k4 + 3) * 64, t);
        }
    }
    #pragma unroll
    for (int j = 0; j < 32; j++) acc[j] = fmaxf(acc[j], 0.f);
    exchange_stage(stage, acc, t);
    initAcc32(acc, s + OFF_LB2, t);
    gemv_stage32(acc, stage, s + OFF_LW2, 64, t);
    #pragma unroll
    for (int j = 0; j < 32; j++) acc[j] = fmaxf(acc[j], 0.f);
    exchange_stage(stage, acc, t);
    gemv_stage32(ca, stage, s + OFF_CMW1 + 192 * 64, 64, t);

    // ----- road / gen / exe (comb rows 256..268) -----
    {
        stage[0]  = o[CUR + 228]; stage[1]  = o[CUR + 229];   // bott
        stage[2]  = o[CUR + 247]; stage[3]  = o[CUR + 248];   // dist_bott
        stage[4]  = o[CUR + 230]; stage[5]  = o[CUR + 231];   // road_end
        stage[6]  = o[CUR + 249]; stage[7]  = o[CUR + 250];   // dist_end
        stage[8]  = o[CUR + 232]; stage[9]  = o[CUR + 233];   // target
        stage[10] = o[CUR + 253];                             // gen
        stage[11] = o[CUR + 251]; stage[12] = o[CUR + 252];   // exe
        gemv_stage32(ca, stage, s + OFF_CMW1 + 256 * 64, 13, t);
    }

    // ----- final layer: relu(relu(ca) @ cmW2 + cmb2) -----
    #pragma unroll
    for (int j = 0; j < 32; j++) ca[j] = fmaxf(ca[j], 0.f);
    exchange_stage(stage, ca, t);
    initAcc32(acc, s + OFF_CMB2, t);
    gemv_stage32(acc, stage, s + OFF_CMW2, 64, t);

    // write owned interleaved chunks: out[b*64 + (2i+t)*4 .. +3]
    float4* op = reinterpret_cast<float4*>(out + (long long)b * 64);
    #pragma unroll
    for (int i = 0; i < 8; i++) {
        float4 q;
        q.x = fmaxf(acc[4*i+0], 0.f);
        q.y = fmaxf(acc[4*i+1], 0.f);
        q.z = fmaxf(acc[4*i+2], 0.f);
        q.w = fmaxf(acc[4*i+3], 0.f);
        op[2 * i + t] = q;
    }
}

extern "C" void kernel_launch(void* const* d_in, const int* in_sizes, int n_in,
                              void* d_out, int out_size) {
    const float* obs    = (const float*)d_in[0];
    const float* W_self = (const float*)d_in[1];
    const float* b_self = (const float*)d_in[2];
    const float* W_dyn  = (const float*)d_in[3];
    const float* b_dyn  = (const float*)d_in[4];
    const float* hWh    = (const float*)d_in[5];
    const float* ha1    = (const float*)d_in[6];
    const float* ha2    = (const float*)d_in[7];
    const float* hWo    = (const float*)d_in[8];
    const float* hao1   = (const float*)d_in[9];
    const float* hao2   = (const float*)d_in[10];
    const float* cWh    = (const float*)d_in[11];
    const float* ca1v   = (const float*)d_in[12];
    const float* ca2v   = (const float*)d_in[13];
    const float* cWo    = (const float*)d_in[14];
    const float* cao1   = (const float*)d_in[15];
    const float* cao2   = (const float*)d_in[16];
    const float* lW1    = (const float*)d_in[17];
    const float* lb1    = (const float*)d_in[18];
    const float* lW2    = (const float*)d_in[19];
    const float* lb2    = (const float*)d_in[20];
    const float* cmW1   = (const float*)d_in[21];
    const float* cmb1   = (const float*)d_in[22];
    const float* cmW2   = (const float*)d_in[23];
    const float* cmb2   = (const float*)d_in[24];

    int B = in_sizes[0] / OBS_STRIDE;
    size_t smem = (size_t)SMEM_FLOATS * sizeof(float);
    cudaFuncSetAttribute(pred_kernel, cudaFuncAttributeMaxDynamicSharedMemorySize, (int)smem);

    dim3 block(BLOCK);
    dim3 grid(GRID);
    pred_kernel<<<grid, block, smem>>>(
        obs, W_self, b_self, W_dyn, b_dyn,
        hWh, ha1, ha2, hWo, hao1, hao2,
        cWh, ca1v, ca2v, cWo, cao1, cao2,
        lW1, lb1, lW2, lb2,
        cmW1, cmb1, cmW2, cmb2,
        (float*)d_out, B);
}

// round 12
// speedup vs baseline: 1.4029x; 1.4029x over previous
#include <cuda_runtime.h>

#define DEV __device__ __forceinline__

// ---------------- shared-memory weight layout (floats) ----------------
static constexpr int OFF_WSELF = 0;                       // 15*128
static constexpr int OFF_BSELF = OFF_WSELF + 15 * 128;    // 128
static constexpr int OFF_WDYN  = OFF_BSELF + 128;         // 128*64
static constexpr int OFF_BDYN  = OFF_WDYN + 128 * 64;     // 64
static constexpr int OFF_HWH   = OFF_BDYN + 64;           // 3*3*16
static constexpr int OFF_HA1   = OFF_HWH + 144;           // 48
static constexpr int OFF_HA2   = OFF_HA1 + 48;            // 48
static constexpr int OFF_HWO   = OFF_HA2 + 48;            // 48*64
static constexpr int OFF_HWA1  = OFF_HWO + 48 * 64;       // 48  (hWo @ hao1)
static constexpr int OFF_HWA2  = OFF_HWA1 + 48;           // 48  (hWo @ hao2)
static constexpr int OFF_CWH   = OFF_HWA2 + 48;
static constexpr int OFF_CA1   = OFF_CWH + 144;
static constexpr int OFF_CA2   = OFF_CA1 + 48;
static constexpr int OFF_CWO   = OFF_CA2 + 48;
static constexpr int OFF_CWA1  = OFF_CWO + 48 * 64;
static constexpr int OFF_CWA2  = OFF_CWA1 + 48;
static constexpr int OFF_LW1   = OFF_CWA2 + 48;           // 108*64
static constexpr int OFF_LB1   = OFF_LW1 + 108 * 64;      // 64
static constexpr int OFF_LW2   = OFF_LB1 + 64;            // 64*64
static constexpr int OFF_LB2   = OFF_LW2 + 64 * 64;       // 64
static constexpr int OFF_CMW1  = OFF_LB2 + 64;            // 269*64
static constexpr int OFF_CMB1  = OFF_CMW1 + 269 * 64;     // 64
static constexpr int OFF_CMW2  = OFF_CMB1 + 64;           // 64*64
static constexpr int OFF_CMB2  = OFF_CMW2 + 64 * 64;      // 64
static constexpr int SMEM_FLOATS = OFF_CMB2 + 64;         // 49696 floats = 198784 B

static constexpr int OBS_STRIDE = 2064;   // 6 * 344
static constexpr int CUR = 5 * 344;       // 1720

static constexpr int ROWS_PER_BLOCK = 224; // = threads; each thread-pair handles 2 rows
static constexpr int BLOCK = 224;          // 7 warps
static constexpr int GRID  = 148;

DEV float lrelu2(float z)  { return z > 0.f ? z : 0.01f * z; }  // leaky(leaky(.,0.1),0.1)
DEV float lrelu02(float z) { return z > 0.f ? z : 0.2f  * z; }
DEV float eluf(float z)    { return z > 0.f ? z : (__expf(z) - 1.f); }

DEV void cp4(float* dst, const float* __restrict__ src, int n4, int tid, int bd) {
    float4* d = reinterpret_cast<float4*>(dst);
    const float4* sp = reinterpret_cast<const float4*>(src);
    for (int i = tid; i < n4; i += bd) d[i] = sp[i];
}

// Dual-row GEMV update: thread owns interleaved float4 chunks (2i+t) of the 64-wide
// output for BOTH rows of its pair. One weight load feeds 8 FMAs (2 rows x 4 cols).
DEV void gv32x2(float (&a0)[32], float (&a1)[32], float v0, float v1,
                const float* row, int t) {
    const float4* w = reinterpret_cast<const float4*>(row);
    #pragma unroll
    for (int i = 0; i < 8; i++) {
        float4 q = w[2 * i + t];
        a0[4*i+0] = fmaf(v0, q.x, a0[4*i+0]);
        a0[4*i+1] = fmaf(v0, q.y, a0[4*i+1]);
        a0[4*i+2] = fmaf(v0, q.z, a0[4*i+2]);
        a0[4*i+3] = fmaf(v0, q.w, a0[4*i+3]);
        a1[4*i+0] = fmaf(v1, q.x, a1[4*i+0]);
        a1[4*i+1] = fmaf(v1, q.y, a1[4*i+1]);
        a1[4*i+2] = fmaf(v1, q.z, a1[4*i+2]);
        a1[4*i+3] = fmaf(v1, q.w, a1[4*i+3]);
    }
}

DEV void initAcc32(float (&acc)[32], const float* bias, int t) {
    const float4* bp = reinterpret_cast<const float4*>(bias);
    #pragma unroll
    for (int i = 0; i < 8; i++) {
        float4 q = bp[2 * i + t];
        acc[4*i+0] = q.x; acc[4*i+1] = q.y; acc[4*i+2] = q.z; acc[4*i+3] = q.w;
    }
}

// Exchange the two column-halves of ONE row between pair threads -> full 64-wide
// multiplier vector in local stage. own[4i+c] is column 8i+4t+c of this row;
// partner's own[4i+c] is column 8i+4(1-t)+c of the SAME row.
DEV void exchange_half(volatile float* st, const float (&own)[32], int t) {
    #pragma unroll
    for (int i = 0; i < 8; i++) {
        #pragma unroll
        for (int c = 0; c < 4; c++) {
            float v = own[4 * i + c];
            float p = __shfl_xor_sync(0xFFFFFFFFu, v, 1);
            st[8 * i + 4 * t + c] = v;
            st[8 * i + 4 * (1 - t) + c] = p;
        }
    }
}

// Dual-row GEMV from full-width stage vectors (row0, row1 multipliers).
DEV void gemv_dual(float (&a0)[32], float (&a1)[32],
                   volatile const float* st0, volatile const float* st1,
                   const float* sW, int K, int t) {
    #pragma unroll 1
    for (int k = 0; k < K; k++) {
        float v0 = st0[k];
        float v1 = st1[k];
        gv32x2(a0, a1, v0, v1, sW + k * 64, t);
    }
}

// Star-GAT collapsed (own row only). Streams x2e/x2o into LOCAL arrays,
// accumulating layer-2 attention dots on the fly. Returns blend weights we/wo.
template<int N>
DEV void gat_collapse(const float* __restrict__ xin,     // nodes 1..N-1, stride 6, first 3 floats
                      float e0, float e1, float e2,      // ego node coords
                      const float* s, int WH, int A1, int A2, int WA1, int WA2,
                      volatile float* lx2e, volatile float* lx2o,
                      float& we_out, float& wo_out)
{
    float d1e = 0.f, d2e = 0.f, d2o = 0.f;
    #pragma unroll 1
    for (int h = 0; h < 3; h++) {
        const float* Wh = s + WH + h * 48;   // [3][16]
        const float* a1 = s + A1 + h * 16;
        const float* a2 = s + A2 + h * 16;
        float h0[16];
        float s1 = 0.f, s20 = 0.f;
        #pragma unroll
        for (int u = 0; u < 16; u++) {
            float hv = fmaf(e0, Wh[u], fmaf(e1, Wh[16 + u], e2 * Wh[32 + u]));
            h0[u] = hv;
            s1  = fmaf(a1[u], hv, s1);
            s20 = fmaf(a2[u], hv, s20);
        }
        float w0 = __expf(lrelu02(s1 + s20));
        float den = w0;
        float ws[16];
        #pragma unroll
        for (int u = 0; u < 16; u++) ws[u] = w0 * h0[u];
        #pragma unroll 1
        for (int m = 0; m < N - 1; m++) {
            const float* xp = xin + m * 6;
            float x0 = xp[0], x1 = xp[1], x2v = xp[2];
            float hm[16]; float s2 = 0.f;
            #pragma unroll
            for (int u = 0; u < 16; u++) {
                float hv = fmaf(x0, Wh[u], fmaf(x1, Wh[16 + u], x2v * Wh[32 + u]));
                hm[u] = hv;
                s2 = fmaf(a2[u], hv, s2);
            }
            float wm = __expf(lrelu02(s1 + s2));
            den += wm;
            #pragma unroll
            for (int u = 0; u < 16; u++) ws[u] = fmaf(wm, hm[u], ws[u]);
        }
        float inv = __fdividef(1.f, den);
        #pragma unroll
        for (int u = 0; u < 16; u++) {
            float xe = eluf(ws[u] * inv);     // ego layer-1 output (concat heads)
            float xo = eluf(h0[u]);           // identical layer-1 output of every non-ego node
            d1e = fmaf(xe, s[WA1 + h * 16 + u], d1e);
            d2e = fmaf(xe, s[WA2 + h * 16 + u], d2e);
            d2o = fmaf(xo, s[WA2 + h * 16 + u], d2o);
            lx2e[h * 16 + u] = xe;
            lx2o[h * 16 + u] = xo;
        }
    }
    float we = __expf(lrelu02(d1e + d2e));
    float wo = (float)(N - 1) * __expf(lrelu02(d1e + d2o));
    float inv = __fdividef(1.f, we + wo);
    we_out = we * inv;
    wo_out = wo * inv;
}

__global__ void __launch_bounds__(BLOCK, 1) pred_kernel(
    const float* __restrict__ obs,
    const float* __restrict__ W_self, const float* __restrict__ b_self,
    const float* __restrict__ W_dyn,  const float* __restrict__ b_dyn,
    const float* __restrict__ hWh, const float* __restrict__ ha1, const float* __restrict__ ha2,
    const float* __restrict__ hWo, const float* __restrict__ hao1, const float* __restrict__ hao2,
    const float* __restrict__ cWh, const float* __restrict__ ca1v, const float* __restrict__ ca2v,
    const float* __restrict__ cWo, const float* __restrict__ cao1, const float* __restrict__ cao2,
    const float* __restrict__ lW1, const float* __restrict__ lb1,
    const float* __restrict__ lW2, const float* __restrict__ lb2,
    const float* __restrict__ cmW1, const float* __restrict__ cmb1,
    const float* __restrict__ cmW2, const float* __restrict__ cmb2,
    float* __restrict__ out, int B)
{
    extern __shared__ float s[];
    const int tid = threadIdx.x, bd = blockDim.x;

    cp4(s + OFF_WSELF, W_self, 15 * 128 / 4, tid, bd);
    cp4(s + OFF_BSELF, b_self, 128 / 4, tid, bd);
    cp4(s + OFF_WDYN,  W_dyn,  128 * 64 / 4, tid, bd);
    cp4(s + OFF_BDYN,  b_dyn,  64 / 4, tid, bd);
    cp4(s + OFF_HWH,   hWh,    144 / 4, tid, bd);
    cp4(s + OFF_HA1,   ha1,    48 / 4, tid, bd);
    cp4(s + OFF_HA2,   ha2,    48 / 4, tid, bd);
    cp4(s + OFF_HWO,   hWo,    48 * 64 / 4, tid, bd);
    cp4(s + OFF_CWH,   cWh,    144 / 4, tid, bd);
    cp4(s + OFF_CA1,   ca1v,   48 / 4, tid, bd);
    cp4(s + OFF_CA2,   ca2v,   48 / 4, tid, bd);
    cp4(s + OFF_CWO,   cWo,    48 * 64 / 4, tid, bd);
    cp4(s + OFF_LW1,   lW1,    108 * 64 / 4, tid, bd);
    cp4(s + OFF_LB1,   lb1,    64 / 4, tid, bd);
    cp4(s + OFF_LW2,   lW2,    64 * 64 / 4, tid, bd);
    cp4(s + OFF_LB2,   lb2,    64 / 4, tid, bd);
    cp4(s + OFF_CMW1,  cmW1,   269 * 64 / 4, tid, bd);
    cp4(s + OFF_CMB1,  cmb1,   64 / 4, tid, bd);
    cp4(s + OFF_CMW2,  cmW2,   64 * 64 / 4, tid, bd);
    cp4(s + OFF_CMB2,  cmb2,   64 / 4, tid, bd);

    // Precompute Wo@ao1 / Wo@ao2 for both GATs (48 values each)
    if (tid < 192) {
        int g = tid / 48;
        int r = tid - g * 48;
        const float* Wo = (g < 2) ? hWo : cWo;
        const float* ao = (g == 0) ? hao1 : (g == 1) ? hao2 : (g == 2) ? cao1 : cao2;
        int dst = (g == 0) ? OFF_HWA1 : (g == 1) ? OFF_HWA2 : (g == 2) ? OFF_CWA1 : OFF_CWA2;
        float sum = 0.f;
        #pragma unroll 1
        for (int j = 0; j < 64; j++) sum = fmaf(Wo[r * 64 + j], ao[j], sum);
        s[dst + r] = sum;
    }
    __syncthreads();

    const int t = tid & 1;                 // pair half (owns column chunks 2i+t, both rows)
    long long base = (long long)blockIdx.x * ROWS_PER_BLOCK + (tid >> 1) * 2;
    if (base + 1 >= B) base = B - 2;       // B even; keep all lanes alive for shfl
    const float* o = obs + (base + t) * OBS_STRIDE;   // this thread's OWN scalar row

    volatile float st0[64];     // full-width multipliers, pair row 0
    volatile float st1[64];     // full-width multipliers, pair row 1
    volatile float lx2e[48];
    volatile float lx2o[48];
    float caR0[32], caR1[32];   // comb hidden accumulators (owned halves, persist)
    float aR0[32],  aR1[32];    // working accumulators

    initAcc32(caR0, s + OFF_CMB1, t);
    initAcc32(caR1, s + OFF_CMB1, t);

    const float e0g = o[CUR + 234], e1g = o[CUR + 235], e2g = o[CUR + 236];

    // ----- HDV GAT (comb rows 64..127) -----
    {
        float we, wo;
        gat_collapse<13>(o + CUR + 0, e0g, e1g, e2g, s, OFF_HWH, OFF_HA1, OFF_HA2,
                         OFF_HWA1, OFF_HWA2, lx2e, lx2o, we, wo);
        #pragma unroll
        for (int j = 0; j < 32; j++) { aR0[j] = 0.f; aR1[j] = 0.f; }
        #pragma unroll 1
        for (int k = 0; k < 48; k++) {
            float own = fmaf(we, lx2e[k], wo * lx2o[k]);
            float par = __shfl_xor_sync(0xFFFFFFFFu, own, 1);
            float v0 = t ? par : own;
            float v1 = t ? own : par;
            gv32x2(aR0, aR1, v0, v1, s + OFF_HWO + k * 64, t);
        }
        #pragma unroll
        for (int j = 0; j < 32; j++) { aR0[j] = eluf(aR0[j]); aR1[j] = eluf(aR1[j]); }
        exchange_half(st0, aR0, t);
        exchange_half(st1, aR1, t);
    }
    gemv_dual(caR0, caR1, st0, st1, s + OFF_CMW1 + 64 * 64, 64, t);

    // ----- CAV GAT (comb rows 128..191) -----
    {
        float we, wo;
        gat_collapse<9>(o + CUR + 72, e0g, e1g, e2g, s, OFF_CWH, OFF_CA1, OFF_CA2,
                        OFF_CWA1, OFF_CWA2, lx2e, lx2o, we, wo);
        #pragma unroll
        for (int j = 0; j < 32; j++) { aR0[j] = 0.f; aR1[j] = 0.f; }
        #pragma unroll 1
        for (int k = 0; k < 48; k++) {
            float own = fmaf(we, lx2e[k], wo * lx2o[k]);
            float par = __shfl_xor_sync(0xFFFFFFFFu, own, 1);
            float v0 = t ? par : own;
            float v1 = t ? own : par;
            gv32x2(aR0, aR1, v0, v1, s + OFF_CWO + k * 64, t);
        }
        #pragma unroll
        for (int j = 0; j < 32; j++) { aR0[j] = eluf(aR0[j]); aR1[j] = eluf(aR1[j]); }
        exchange_half(st0, aR0, t);
        exchange_half(st1, aR1, t);
    }
    gemv_dual(caR0, caR1, st0, st1, s + OFF_CMW1 + 128 * 64, 64, t);

    // ----- ego feature (comb rows 0..63): leaky2(ehist@W_self+b_self)@W_dyn+b_dyn -----
    initAcc32(aR0, s + OFF_BDYN, t);
    initAcc32(aR1, s + OFF_BDYN, t);
    {
        float eh[15];
        #pragma unroll
        for (int st = 0; st < 5; st++) {
            const float* p = o + (st + 1) * 344 + 234;   // own row history
            eh[st * 3 + 0] = p[0];
            eh[st * 3 + 1] = p[1];
            eh[st * 3 + 2] = p[2];
        }
        #pragma unroll 1
        for (int kg = 0; kg < 32; kg++) {   // 4 hidden columns at a time (float4 rows)
            float4 zb = reinterpret_cast<const float4*>(s + OFF_BSELF)[kg];
            float z0 = zb.x, z1 = zb.y, z2 = zb.z, z3 = zb.w;
            #pragma unroll
            for (int i = 0; i < 15; i++) {
                float4 w = reinterpret_cast<const float4*>(s + OFF_WSELF + i * 128)[kg];
                z0 = fmaf(eh[i], w.x, z0);
                z1 = fmaf(eh[i], w.y, z1);
                z2 = fmaf(eh[i], w.z, z2);
                z3 = fmaf(eh[i], w.w, z3);
            }
            z0 = lrelu2(z0); z1 = lrelu2(z1); z2 = lrelu2(z2); z3 = lrelu2(z3);
            float p0 = __shfl_xor_sync(0xFFFFFFFFu, z0, 1);
            float p1 = __shfl_xor_sync(0xFFFFFFFFu, z1, 1);
            float p2 = __shfl_xor_sync(0xFFFFFFFFu, z2, 1);
            float p3 = __shfl_xor_sync(0xFFFFFFFFu, z3, 1);
            gv32x2(aR0, aR1, t ? p0 : z0, t ? z0 : p0, s + OFF_WDYN + (4 * kg + 0) * 64, t);
            gv32x2(aR0, aR1, t ? p1 : z1, t ? z1 : p1, s + OFF_WDYN + (4 * kg + 1) * 64, t);
            gv32x2(aR0, aR1, t ? p2 : z2, t ? z2 : p2, s + OFF_WDYN + (4 * kg + 2) * 64, t);
            gv32x2(aR0, aR1, t ? p3 : z3, t ? z3 : p3, s + OFF_WDYN + (4 * kg + 3) * 64, t);
        }
    }
    exchange_half(st0, aR0, t);    // ego out has NO nonlinearity
    exchange_half(st1, aR1, t);
    gemv_dual(caR0, caR1, st0, st1, s + OFF_CMW1 + 0 * 64, 64, t);

    // ----- lane MLP (comb rows 192..255) -----
    initAcc32(aR0, s + OFF_LB1, t);
    initAcc32(aR1, s + OFF_LB1, t);
    {
        const float4* lp = reinterpret_cast<const float4*>(o + CUR + 120);  // own row lane data
        #pragma unroll 1
        for (int k4 = 0; k4 < 27; k4++) {
            float4 v = lp[k4];
            float px = __shfl_xor_sync(0xFFFFFFFFu, v.x, 1);
            float py = __shfl_xor_sync(0xFFFFFFFFu, v.y, 1);
            float pz = __shfl_xor_sync(0xFFFFFFFFu, v.z, 1);
            float pw = __shfl_xor_sync(0xFFFFFFFFu, v.w, 1);
            gv32x2(aR0, aR1, t ? px : v.x, t ? v.x : px, s + OFF_LW1 + (4 * k4 + 0) * 64, t);
            gv32x2(aR0, aR1, t ? py : v.y, t ? v.y : py, s + OFF_LW1 + (4 * k4 + 1) * 64, t);
            gv32x2(aR0, aR1, t ? pz : v.z, t ? v.z : pz, s + OFF_LW1 + (4 * k4 + 2) * 64, t);
            gv32x2(aR0, aR1, t ? pw : v.w, t ? v.w : pw, s + OFF_LW1 + (4 * k4 + 3) * 64, t);
        }
    }
    #pragma unroll
    for (int j = 0; j < 32; j++) { aR0[j] = fmaxf(aR0[j], 0.f); aR1[j] = fmaxf(aR1[j], 0.f); }
    exchange_half(st0, aR0, t);
    exchange_half(st1, aR1, t);
    initAcc32(aR0, s + OFF_LB2, t);
    initAcc32(aR1, s + OFF_LB2, t);
    gemv_dual(aR0, aR1, st0, st1, s + OFF_LW2, 64, t);
    #pragma unroll
    for (int j = 0; j < 32; j++) { aR0[j] = fmaxf(aR0[j], 0.f); aR1[j] = fmaxf(aR1[j], 0.f); }
    exchange_half(st0, aR0, t);
    exchange_half(st1, aR1, t);
    gemv_dual(caR0, caR1, st0, st1, s + OFF_CMW1 + 192 * 64, 64, t);

    // ----- road / gen / exe (comb rows 256..268) -----
    {
        float rv[13];
        rv[0]  = o[CUR + 228]; rv[1]  = o[CUR + 229];   // bott
        rv[2]  = o[CUR + 247]; rv[3]  = o[CUR + 248];   // dist_bott
        rv[4]  = o[CUR + 230]; rv[5]  = o[CUR + 231];   // road_end
        rv[6]  = o[CUR + 249]; rv[7]  = o[CUR + 250];   // dist_end
        rv[8]  = o[CUR + 232]; rv[9]  = o[CUR + 233];   // target
        rv[10] = o[CUR + 253];                          // gen
        rv[11] = o[CUR + 251]; rv[12] = o[CUR + 252];   // exe
        #pragma unroll 1
        for (int k = 0; k < 13; k++) {
            float own = rv[k];
            float par = __shfl_xor_sync(0xFFFFFFFFu, own, 1);
            gv32x2(caR0, caR1, t ? par : own, t ? own : par, s + OFF_CMW1 + (256 + k) * 64, t);
        }
    }

    // ----- final layer: relu(relu(ca) @ cmW2 + cmb2) -----
    #pragma unroll
    for (int j = 0; j < 32; j++) { caR0[j] = fmaxf(caR0[j], 0.f); caR1[j] = fmaxf(caR1[j], 0.f); }
    exchange_half(st0, caR0, t);
    exchange_half(st1, caR1, t);
    initAcc32(aR0, s + OFF_CMB2, t);
    initAcc32(aR1, s + OFF_CMB2, t);
    gemv_dual(aR0, aR1, st0, st1, s + OFF_CMW2, 64, t);

    // write owned interleaved chunks of both rows
    float4* op0 = reinterpret_cast<float4*>(out + base * 64);
    float4* op1 = reinterpret_cast<float4*>(out + (base + 1) * 64);
    #pragma unroll
    for (int i = 0; i < 8; i++) {
        float4 q0, q1;
        q0.x = fmaxf(aR0[4*i+0], 0.f); q0.y = fmaxf(aR0[4*i+1], 0.f);
        q0.z = fmaxf(aR0[4*i+2], 0.f); q0.w = fmaxf(aR0[4*i+3], 0.f);
        q1.x = fmaxf(aR1[4*i+0], 0.f); q1.y = fmaxf(aR1[4*i+1], 0.f);
        q1.z = fmaxf(aR1[4*i+2], 0.f); q1.w = fmaxf(aR1[4*i+3], 0.f);
        op0[2 * i + t] = q0;
        op1[2 * i + t] = q1;
    }
}

extern "C" void kernel_launch(void* const* d_in, const int* in_sizes, int n_in,
                              void* d_out, int out_size) {
    const float* obs    = (const float*)d_in[0];
    const float* W_self = (const float*)d_in[1];
    const float* b_self = (const float*)d_in[2];
    const float* W_dyn  = (const float*)d_in[3];
    const float* b_dyn  = (const float*)d_in[4];
    const float* hWh    = (const float*)d_in[5];
    const float* ha1    = (const float*)d_in[6];
    const float* ha2    = (const float*)d_in[7];
    const float* hWo    = (const float*)d_in[8];
    const float* hao1   = (const float*)d_in[9];
    const float* hao2   = (const float*)d_in[10];
    const float* cWh    = (const float*)d_in[11];
    const float* ca1v   = (const float*)d_in[12];
    const float* ca2v   = (const float*)d_in[13];
    const float* cWo    = (const float*)d_in[14];
    const float* cao1   = (const float*)d_in[15];
    const float* cao2   = (const float*)d_in[16];
    const float* lW1    = (const float*)d_in[17];
    const float* lb1    = (const float*)d_in[18];
    const float* lW2    = (const float*)d_in[19];
    const float* lb2    = (const float*)d_in[20];
    const float* cmW1   = (const float*)d_in[21];
    const float* cmb1   = (const float*)d_in[22];
    const float* cmW2   = (const float*)d_in[23];
    const float* cmb2   = (const float*)d_in[24];

    int B = in_sizes[0] / OBS_STRIDE;
    size_t smem = (size_t)SMEM_FLOATS * sizeof(float);
    cudaFuncSetAttribute(pred_kernel, cudaFuncAttributeMaxDynamicSharedMemorySize, (int)smem);

    dim3 block(BLOCK);
    dim3 grid(GRID);
    pred_kernel<<<grid, block, smem>>>(
        obs, W_self, b_self, W_dyn, b_dyn,
        hWh, ha1, ha2, hWo, hao1, hao2,
        cWh, ca1v, ca2v, cWo, cao1, cao2,
        lW1, lb1, lW2, lb2,
        cmW1, cmb1, cmW2, cmb2,
        (float*)d_out, B);
}